// round 12
// baseline (speedup 1.0000x reference)
#include <cuda_runtime.h>
#include <cuda_bf16.h>
#include <cstdint>

#define NVERT    16384
#define BLOCK    1024
#define GRID     148
#define NWARPS   (GRID * (BLOCK / 32))      // 4736
#define SMEM_BYTES (3 * NVERT * sizeof(float))   // 196608 B

// Tier A: row-pairs 0..7679, units = pair x 4 quarters of 4096 cols (32 KB)
#define A_PAIRS   7680
#define A_UNITS   (A_PAIRS * 4)          // 30720
#define A_COLS    4096
// Tier B1 (drain): rows 15360..16127, 1 row x 16 slices of 1024 cols (4 KB)
#define B1_ROWS   768
#define B1_ROW0   (2 * A_PAIRS)          // 15360
#define B1_SLICES 16
#define B1_COLS   1024
#define B1_UNITS  (B1_ROWS * B1_SLICES)  // 12288
// Tier B2 (final drain): rows 16128..16383, 1 row x 32 slices of 512 cols (2 KB)
#define B2_ROWS   256
#define B2_ROW0   (B1_ROW0 + B1_ROWS)    // 16128
#define B2_SLICES 32
#define B2_COLS   512
#define B2_UNITS  (B2_ROWS * B2_SLICES)  // 8192
#define NUNITS    (A_UNITS + B1_UNITS + B2_UNITS)   // 51200

// Deterministic partials.
__device__ float g_y4 [4 * NVERT * 3];              // tier A:  [q][row][comp]
__device__ float g_yB1[B1_SLICES * B1_ROWS * 3];    // tier B1: [s][lrow][comp]
__device__ float g_yB2[B2_SLICES * B2_ROWS * 3];    // tier B2: [s][lrow][comp]
// Work-stealing state (self-resetting for graph replays)
__device__ unsigned int g_ticket = 0;
__device__ unsigned int g_done   = 0;

// 1-row unit body (tiers B1/B2): dot 1 row of L against 3 x-components.
__device__ __forceinline__ void row_unit(
    const float4* __restrict__ r0, const float* __restrict__ sx,
    int colbase, int niter, int lane, float* dst)
{
    const float4* __restrict__ xs0 = (const float4*)(sx + 0 * NVERT + colbase);
    const float4* __restrict__ xs1 = (const float4*)(sx + 1 * NVERT + colbase);
    const float4* __restrict__ xs2 = (const float4*)(sx + 2 * NVERT + colbase);

    float b0 = 0.f, b1 = 0.f, b2 = 0.f;
    #pragma unroll 4
    for (int i = lane; i < niter; i += 32) {
        float4 l0 = __ldcs(r0 + i);
        float4 v0 = xs0[i];
        float4 v1 = xs1[i];
        float4 v2 = xs2[i];
        b0 += l0.x * v0.x + l0.y * v0.y + l0.z * v0.z + l0.w * v0.w;
        b1 += l0.x * v1.x + l0.y * v1.y + l0.z * v1.z + l0.w * v1.w;
        b2 += l0.x * v2.x + l0.y * v2.y + l0.z * v2.z + l0.w * v2.w;
    }
    #pragma unroll
    for (int off = 16; off > 0; off >>= 1) {
        b0 += __shfl_xor_sync(0xFFFFFFFFu, b0, off);
        b1 += __shfl_xor_sync(0xFFFFFFFFu, b1, off);
        b2 += __shfl_xor_sync(0xFFFFFFFFu, b2, off);
    }
    if (lane < 3) {
        float v = (lane == 0) ? b0 : (lane == 1) ? b1 : b2;
        dst[lane] = v;
    }
}

__global__ void __launch_bounds__(BLOCK, 1)
lap_main_kernel(const float* __restrict__ L, const float* __restrict__ x,
                float* __restrict__ out) {
    extern __shared__ float sx[];   // SoA: [3][NVERT]

    if (blockIdx.x == 0 && threadIdx.x == 0) out[0] = 0.0f;

    const int lane = threadIdx.x & 31;
    const int gw   = blockIdx.x * (BLOCK / 32) + (threadIdx.x >> 5);

    // Prefetch the head of this warp's FIRST (static) unit into L2 while x is
    // being staged, so the streaming loop opens on L2 hits instead of idle DRAM.
    {
        const unsigned int u0 = (unsigned int)gw;     // < A_UNITS always
        const int p = (int)(u0 >> 2);
        const int q = (int)(u0 & 3);
        const float* r0 = L + (size_t)(2 * p) * NVERT + q * A_COLS;
        const float* r1 = r0 + NVERT;
        #pragma unroll
        for (int k = 0; k < 4; k++) {
            const float* p0 = r0 + 4 * (lane + 32 * k);
            const float* p1 = r1 + 4 * (lane + 32 * k);
            asm volatile("prefetch.global.L2 [%0];" :: "l"(p0));
            asm volatile("prefetch.global.L2 [%0];" :: "l"(p1));
        }
    }

    // Stage x into shared memory via float4 global loads, SoA scatter.
    {
        const float4* __restrict__ xv = (const float4*)x;
        for (int j = threadIdx.x; j < (NVERT * 3) / 4; j += BLOCK) {
            float4 v = xv[j];
            int base = 4 * j;
            float f[4] = {v.x, v.y, v.z, v.w};
            #pragma unroll
            for (int k = 0; k < 4; k++) {
                int e    = base + k;
                int vert = e / 3;
                int c    = e - 3 * vert;
                sx[c * NVERT + vert] = f[k];
            }
        }
    }
    __syncthreads();

    // First unit is static (u = gw); subsequent units come from the ticket
    // counter shifted by NWARPS. The next ticket is fetched BEFORE processing
    // the current unit so the atomic's latency hides under the streaming.
    unsigned int u = (unsigned int)gw;
    for (;;) {
        unsigned int nxt = 0;
        if (lane == 0) nxt = NWARPS + atomicAdd(&g_ticket, 1u);

        if (u < A_UNITS) {
            // ---- Tier A: 2 rows x 4096 cols ----
            const int p = (int)(u >> 2);
            const int q = (int)(u & 3);
            const int row0 = 2 * p;
            const int colbase = q * A_COLS;

            const float4* __restrict__ r0 =
                (const float4*)(L + (size_t)row0 * NVERT + colbase);
            const float4* __restrict__ r1 = r0 + (NVERT / 4);
            const float4* __restrict__ xs0 = (const float4*)(sx + 0 * NVERT + colbase);
            const float4* __restrict__ xs1 = (const float4*)(sx + 1 * NVERT + colbase);
            const float4* __restrict__ xs2 = (const float4*)(sx + 2 * NVERT + colbase);

            float a00 = 0.f, a01 = 0.f, a02 = 0.f;
            float a10 = 0.f, a11 = 0.f, a12 = 0.f;

            #pragma unroll 4
            for (int i = lane; i < A_COLS / 4; i += 32) {
                float4 l0 = __ldcs(r0 + i);   // streaming: L has zero reuse
                float4 l1 = __ldcs(r1 + i);
                float4 v0 = xs0[i];
                float4 v1 = xs1[i];
                float4 v2 = xs2[i];

                a00 += l0.x * v0.x + l0.y * v0.y + l0.z * v0.z + l0.w * v0.w;
                a01 += l0.x * v1.x + l0.y * v1.y + l0.z * v1.z + l0.w * v1.w;
                a02 += l0.x * v2.x + l0.y * v2.y + l0.z * v2.z + l0.w * v2.w;
                a10 += l1.x * v0.x + l1.y * v0.y + l1.z * v0.z + l1.w * v0.w;
                a11 += l1.x * v1.x + l1.y * v1.y + l1.z * v1.z + l1.w * v1.w;
                a12 += l1.x * v2.x + l1.y * v2.y + l1.z * v2.z + l1.w * v2.w;
            }

            #pragma unroll
            for (int off = 16; off > 0; off >>= 1) {
                a00 += __shfl_xor_sync(0xFFFFFFFFu, a00, off);
                a01 += __shfl_xor_sync(0xFFFFFFFFu, a01, off);
                a02 += __shfl_xor_sync(0xFFFFFFFFu, a02, off);
                a10 += __shfl_xor_sync(0xFFFFFFFFu, a10, off);
                a11 += __shfl_xor_sync(0xFFFFFFFFu, a11, off);
                a12 += __shfl_xor_sync(0xFFFFFFFFu, a12, off);
            }

            if (lane < 6) {
                float v;
                switch (lane) {
                    case 0: v = a00; break;
                    case 1: v = a01; break;
                    case 2: v = a02; break;
                    case 3: v = a10; break;
                    case 4: v = a11; break;
                    default: v = a12; break;
                }
                const int row = row0 + (lane >= 3 ? 1 : 0);
                const int c   = (lane >= 3) ? (lane - 3) : lane;
                g_y4[(q * NVERT + row) * 3 + c] = v;
            }
        } else if (u < A_UNITS + B1_UNITS) {
            // ---- Tier B1: 1 row x 1024 cols ----
            const unsigned int t = u - A_UNITS;
            const int lrow = (int)(t >> 4);
            const int s    = (int)(t & (B1_SLICES - 1));
            const int row  = B1_ROW0 + lrow;
            const int colbase = s * B1_COLS;
            const float4* __restrict__ r0 =
                (const float4*)(L + (size_t)row * NVERT + colbase);
            row_unit(r0, sx, colbase, B1_COLS / 4, lane,
                     &g_yB1[(s * B1_ROWS + lrow) * 3]);
        } else {
            // ---- Tier B2 (final drain): 1 row x 512 cols ----
            const unsigned int t = u - (A_UNITS + B1_UNITS);
            const int lrow = (int)(t >> 5);
            const int s    = (int)(t & (B2_SLICES - 1));
            const int row  = B2_ROW0 + lrow;
            const int colbase = s * B2_COLS;
            const float4* __restrict__ r0 =
                (const float4*)(L + (size_t)row * NVERT + colbase);
            row_unit(r0, sx, colbase, B2_COLS / 4, lane,
                     &g_yB2[(s * B2_ROWS + lrow) * 3]);
        }

        nxt = __shfl_sync(0xFFFFFFFFu, nxt, 0);
        if (nxt >= NUNITS) break;
        u = nxt;
    }

    // Self-reset: last warp restores counters for the next graph replay.
    if (lane == 0) {
        __threadfence();
        unsigned int d = atomicAdd(&g_done, 1u);
        if (d == NWARPS - 1) {
            g_ticket = 0;
            g_done   = 0;
            __threadfence();
        }
    }

    // PDL: allow the dependent pass2 grid to be scheduled during the drain.
    asm volatile("griddepcontrol.launch_dependents;" ::: "memory");
}

__global__ void __launch_bounds__(256)
pass2_kernel(float* __restrict__ out) {
    // PDL: block until the primary grid fully completes (partials visible).
    asm volatile("griddepcontrol.wait;" ::: "memory");

    __shared__ float red[8];
    float s = 0.f;
    const int stride = gridDim.x * blockDim.x;
    const int tid = blockIdx.x * blockDim.x + threadIdx.x;

    // Tier A region: rows 0..15359 -> 11520 float4 per q-slice (stride 12288).
    {
        const float4* __restrict__ yv = (const float4*)g_y4;
        const int totalA = (B1_ROW0 * 3) / 4;            // 11520
        const int sliceStride = (NVERT * 3) / 4;         // 12288
        for (int i = tid; i < totalA; i += stride) {
            float4 a = yv[i];
            float4 b = yv[i + sliceStride];
            float4 c = yv[i + 2 * sliceStride];
            float4 d = yv[i + 3 * sliceStride];
            float vx = a.x + b.x + c.x + d.x;
            float vy = a.y + b.y + c.y + d.y;
            float vz = a.z + b.z + c.z + d.z;
            float vw = a.w + b.w + c.w + d.w;
            s += vx * vx + vy * vy + vz * vz + vw * vw;
        }
    }
    // Tier B1 region: 768 rows -> 576 float4 per slice, 16 slices.
    {
        const float4* __restrict__ yv = (const float4*)g_yB1;
        const int totalB = (B1_ROWS * 3) / 4;            // 576
        for (int i = tid; i < totalB; i += stride) {
            float4 a = yv[i];
            #pragma unroll
            for (int j = 1; j < B1_SLICES; j++) {
                float4 b = yv[i + j * totalB];
                a.x += b.x; a.y += b.y; a.z += b.z; a.w += b.w;
            }
            s += a.x * a.x + a.y * a.y + a.z * a.z + a.w * a.w;
        }
    }
    // Tier B2 region: 256 rows -> 192 float4 per slice, 32 slices.
    {
        const float4* __restrict__ yv = (const float4*)g_yB2;
        const int totalB = (B2_ROWS * 3) / 4;            // 192
        for (int i = tid; i < totalB; i += stride) {
            float4 a = yv[i];
            #pragma unroll
            for (int j = 1; j < B2_SLICES; j++) {
                float4 b = yv[i + j * totalB];
                a.x += b.x; a.y += b.y; a.z += b.z; a.w += b.w;
            }
            s += a.x * a.x + a.y * a.y + a.z * a.z + a.w * a.w;
        }
    }

    #pragma unroll
    for (int off = 16; off > 0; off >>= 1)
        s += __shfl_xor_sync(0xFFFFFFFFu, s, off);
    const int lane = threadIdx.x & 31;
    const int wid  = threadIdx.x >> 5;
    if (lane == 0) red[wid] = s;
    __syncthreads();
    if (wid == 0) {
        int nwarps = blockDim.x >> 5;
        float t = (lane < nwarps) ? red[lane] : 0.f;
        #pragma unroll
        for (int off = 16; off > 0; off >>= 1)
            t += __shfl_xor_sync(0xFFFFFFFFu, t, off);
        if (lane == 0) atomicAdd(out, t);
    }
}

extern "C" void kernel_launch(void* const* d_in, const int* in_sizes, int n_in,
                              void* d_out, int out_size) {
    // Identify inputs by element count: x has NVERT*3, L has NVERT*NVERT.
    const float* x = (const float*)d_in[0];
    const float* L = (const float*)d_in[1];
    if (in_sizes[0] != NVERT * 3) {
        x = (const float*)d_in[1];
        L = (const float*)d_in[0];
    }
    float* out = (float*)d_out;

    cudaFuncSetAttribute(lap_main_kernel,
                         cudaFuncAttributeMaxDynamicSharedMemorySize,
                         (int)SMEM_BYTES);

    lap_main_kernel<<<GRID, BLOCK, SMEM_BYTES>>>(L, x, out);

    // pass2 with Programmatic Dependent Launch: its 148 blocks are prescheduled
    // during the primary's drain and start the instant the primary completes.
    cudaLaunchConfig_t cfg = {};
    cfg.gridDim  = dim3(148, 1, 1);
    cfg.blockDim = dim3(256, 1, 1);
    cfg.dynamicSmemBytes = 0;
    cfg.stream = 0;   // same (capture) stream as the primary launch
    cudaLaunchAttribute attrs[1];
    attrs[0].id = cudaLaunchAttributeProgrammaticStreamSerialization;
    attrs[0].val.programmaticStreamSerializationAllowed = 1;
    cfg.attrs = attrs;
    cfg.numAttrs = 1;
    cudaLaunchKernelEx(&cfg, pass2_kernel, out);
}

// round 13
// speedup vs baseline: 1.0852x; 1.0852x over previous
#include <cuda_runtime.h>
#include <cuda_bf16.h>
#include <cstdint>

#define NVERT    16384
#define BLOCK    1024
#define GRID     148
#define NWARPS   (GRID * (BLOCK / 32))      // 4736
#define SMEM_BYTES (3 * NVERT * sizeof(float))   // 196608 B

// Tier A: row-pairs 0..7679, units = pair x 4 quarters of 4096 cols (32 KB)
#define A_PAIRS   7680
#define A_UNITS   (A_PAIRS * 4)          // 30720
#define A_COLS    4096
// Tier B (drain tail): rows 15360..16383, units = 1 row x 16 slices of 1024 cols (4 KB)
#define B_ROWS    1024
#define B_ROW0    (2 * A_PAIRS)          // 15360
#define B_SLICES  16
#define B_COLS    1024
#define B_UNITS   (B_ROWS * B_SLICES)    // 16384
#define NUNITS    (A_UNITS + B_UNITS)    // 47104

// Deterministic partials.
__device__ float g_y4[4 * NVERT * 3];             // tier A: [q][row][comp]
__device__ float g_yB[B_SLICES * B_ROWS * 3];     // tier B: [s][lrow][comp]
// Work-stealing state (self-resetting for graph replays)
__device__ unsigned int g_ticket = 0;
__device__ unsigned int g_done   = 0;

__global__ void __launch_bounds__(BLOCK, 1)
lap_main_kernel(const float* __restrict__ L, const float* __restrict__ x,
                float* __restrict__ out) {
    extern __shared__ float sx[];   // SoA: [3][NVERT]

    if (blockIdx.x == 0 && threadIdx.x == 0) out[0] = 0.0f;

    const int lane = threadIdx.x & 31;
    const int gw   = blockIdx.x * (BLOCK / 32) + (threadIdx.x >> 5);

    // Prefetch the head of this warp's FIRST (static) unit into L2 while x is
    // being staged, so the streaming loop opens on L2 hits instead of idle DRAM.
    {
        const unsigned int u0 = (unsigned int)gw;     // < A_UNITS always
        const int p = (int)(u0 >> 2);
        const int q = (int)(u0 & 3);
        const float* r0 = L + (size_t)(2 * p) * NVERT + q * A_COLS;
        const float* r1 = r0 + NVERT;
        #pragma unroll
        for (int k = 0; k < 4; k++) {
            const float* p0 = r0 + 4 * (lane + 32 * k);
            const float* p1 = r1 + 4 * (lane + 32 * k);
            asm volatile("prefetch.global.L2 [%0];" :: "l"(p0));
            asm volatile("prefetch.global.L2 [%0];" :: "l"(p1));
        }
    }

    // Stage x into shared memory via float4 global loads, SoA scatter.
    {
        const float4* __restrict__ xv = (const float4*)x;
        for (int j = threadIdx.x; j < (NVERT * 3) / 4; j += BLOCK) {
            float4 v = xv[j];
            int base = 4 * j;
            float f[4] = {v.x, v.y, v.z, v.w};
            #pragma unroll
            for (int k = 0; k < 4; k++) {
                int e    = base + k;
                int vert = e / 3;
                int c    = e - 3 * vert;
                sx[c * NVERT + vert] = f[k];
            }
        }
    }
    __syncthreads();

    // First unit is static (u = gw); subsequent units come from the ticket
    // counter shifted by NWARPS. The next ticket is fetched BEFORE processing
    // the current unit so the atomic's latency hides under ~20us of streaming.
    unsigned int u = (unsigned int)gw;
    for (;;) {
        unsigned int nxt = 0;
        if (lane == 0) nxt = NWARPS + atomicAdd(&g_ticket, 1u);

        if (u < A_UNITS) {
            // ---- Tier A: 2 rows x 4096 cols ----
            const int p = (int)(u >> 2);
            const int q = (int)(u & 3);
            const int row0 = 2 * p;
            const int colbase = q * A_COLS;

            const float4* __restrict__ r0 =
                (const float4*)(L + (size_t)row0 * NVERT + colbase);
            const float4* __restrict__ r1 = r0 + (NVERT / 4);
            const float4* __restrict__ xs0 = (const float4*)(sx + 0 * NVERT + colbase);
            const float4* __restrict__ xs1 = (const float4*)(sx + 1 * NVERT + colbase);
            const float4* __restrict__ xs2 = (const float4*)(sx + 2 * NVERT + colbase);

            float a00 = 0.f, a01 = 0.f, a02 = 0.f;
            float a10 = 0.f, a11 = 0.f, a12 = 0.f;

            #pragma unroll 4
            for (int i = lane; i < A_COLS / 4; i += 32) {
                float4 l0 = __ldcs(r0 + i);   // streaming: L has zero reuse
                float4 l1 = __ldcs(r1 + i);
                float4 v0 = xs0[i];
                float4 v1 = xs1[i];
                float4 v2 = xs2[i];

                a00 += l0.x * v0.x + l0.y * v0.y + l0.z * v0.z + l0.w * v0.w;
                a01 += l0.x * v1.x + l0.y * v1.y + l0.z * v1.z + l0.w * v1.w;
                a02 += l0.x * v2.x + l0.y * v2.y + l0.z * v2.z + l0.w * v2.w;
                a10 += l1.x * v0.x + l1.y * v0.y + l1.z * v0.z + l1.w * v0.w;
                a11 += l1.x * v1.x + l1.y * v1.y + l1.z * v1.z + l1.w * v1.w;
                a12 += l1.x * v2.x + l1.y * v2.y + l1.z * v2.z + l1.w * v2.w;
            }

            #pragma unroll
            for (int off = 16; off > 0; off >>= 1) {
                a00 += __shfl_xor_sync(0xFFFFFFFFu, a00, off);
                a01 += __shfl_xor_sync(0xFFFFFFFFu, a01, off);
                a02 += __shfl_xor_sync(0xFFFFFFFFu, a02, off);
                a10 += __shfl_xor_sync(0xFFFFFFFFu, a10, off);
                a11 += __shfl_xor_sync(0xFFFFFFFFu, a11, off);
                a12 += __shfl_xor_sync(0xFFFFFFFFu, a12, off);
            }

            if (lane < 6) {
                float v;
                switch (lane) {
                    case 0: v = a00; break;
                    case 1: v = a01; break;
                    case 2: v = a02; break;
                    case 3: v = a10; break;
                    case 4: v = a11; break;
                    default: v = a12; break;
                }
                const int row = row0 + (lane >= 3 ? 1 : 0);
                const int c   = (lane >= 3) ? (lane - 3) : lane;
                g_y4[(q * NVERT + row) * 3 + c] = v;
            }
        } else {
            // ---- Tier B (drain tail): 1 row x 1024 cols ----
            const unsigned int t = u - A_UNITS;
            const int lrow = (int)(t >> 4);
            const int s    = (int)(t & (B_SLICES - 1));
            const int row  = B_ROW0 + lrow;
            const int colbase = s * B_COLS;

            const float4* __restrict__ r0 =
                (const float4*)(L + (size_t)row * NVERT + colbase);
            const float4* __restrict__ xs0 = (const float4*)(sx + 0 * NVERT + colbase);
            const float4* __restrict__ xs1 = (const float4*)(sx + 1 * NVERT + colbase);
            const float4* __restrict__ xs2 = (const float4*)(sx + 2 * NVERT + colbase);

            float b0 = 0.f, b1 = 0.f, b2 = 0.f;

            #pragma unroll 4
            for (int i = lane; i < B_COLS / 4; i += 32) {
                float4 l0 = __ldcs(r0 + i);
                float4 v0 = xs0[i];
                float4 v1 = xs1[i];
                float4 v2 = xs2[i];
                b0 += l0.x * v0.x + l0.y * v0.y + l0.z * v0.z + l0.w * v0.w;
                b1 += l0.x * v1.x + l0.y * v1.y + l0.z * v1.z + l0.w * v1.w;
                b2 += l0.x * v2.x + l0.y * v2.y + l0.z * v2.z + l0.w * v2.w;
            }

            #pragma unroll
            for (int off = 16; off > 0; off >>= 1) {
                b0 += __shfl_xor_sync(0xFFFFFFFFu, b0, off);
                b1 += __shfl_xor_sync(0xFFFFFFFFu, b1, off);
                b2 += __shfl_xor_sync(0xFFFFFFFFu, b2, off);
            }

            if (lane < 3) {
                float v = (lane == 0) ? b0 : (lane == 1) ? b1 : b2;
                g_yB[(s * B_ROWS + lrow) * 3 + lane] = v;
            }
        }

        nxt = __shfl_sync(0xFFFFFFFFu, nxt, 0);
        if (nxt >= NUNITS) break;
        u = nxt;
    }

    // Self-reset: last warp restores counters for the next graph replay.
    if (lane == 0) {
        __threadfence();
        unsigned int d = atomicAdd(&g_done, 1u);
        if (d == NWARPS - 1) {
            g_ticket = 0;
            g_done   = 0;
            __threadfence();
        }
    }

    // PDL: allow the dependent pass2 grid to be scheduled during the drain.
    asm volatile("griddepcontrol.launch_dependents;" ::: "memory");
}

__global__ void __launch_bounds__(256)
pass2_kernel(float* __restrict__ out) {
    // PDL: block until the primary grid fully completes (partials visible).
    asm volatile("griddepcontrol.wait;" ::: "memory");

    __shared__ float red[8];
    float s = 0.f;
    const int stride = gridDim.x * blockDim.x;
    const int tid = blockIdx.x * blockDim.x + threadIdx.x;

    // Tier A region: rows 0..15359 -> 11520 float4 per q-slice (stride 12288).
    {
        const float4* __restrict__ yv = (const float4*)g_y4;
        const int totalA = (B_ROW0 * 3) / 4;             // 11520
        const int sliceStride = (NVERT * 3) / 4;         // 12288
        for (int i = tid; i < totalA; i += stride) {
            float4 a = yv[i];
            float4 b = yv[i + sliceStride];
            float4 c = yv[i + 2 * sliceStride];
            float4 d = yv[i + 3 * sliceStride];
            float vx = a.x + b.x + c.x + d.x;
            float vy = a.y + b.y + c.y + d.y;
            float vz = a.z + b.z + c.z + d.z;
            float vw = a.w + b.w + c.w + d.w;
            s += vx * vx + vy * vy + vz * vz + vw * vw;
        }
    }
    // Tier B region: 1024 rows -> 768 float4 per slice, 16 slices.
    {
        const float4* __restrict__ yv = (const float4*)g_yB;
        const int totalB = (B_ROWS * 3) / 4;             // 768
        for (int i = tid; i < totalB; i += stride) {
            float4 a = yv[i];
            #pragma unroll
            for (int j = 1; j < B_SLICES; j++) {
                float4 b = yv[i + j * totalB];
                a.x += b.x; a.y += b.y; a.z += b.z; a.w += b.w;
            }
            s += a.x * a.x + a.y * a.y + a.z * a.z + a.w * a.w;
        }
    }

    #pragma unroll
    for (int off = 16; off > 0; off >>= 1)
        s += __shfl_xor_sync(0xFFFFFFFFu, s, off);
    const int lane = threadIdx.x & 31;
    const int wid  = threadIdx.x >> 5;
    if (lane == 0) red[wid] = s;
    __syncthreads();
    if (wid == 0) {
        int nwarps = blockDim.x >> 5;
        float t = (lane < nwarps) ? red[lane] : 0.f;
        #pragma unroll
        for (int off = 16; off > 0; off >>= 1)
            t += __shfl_xor_sync(0xFFFFFFFFu, t, off);
        if (lane == 0) atomicAdd(out, t);
    }
}

extern "C" void kernel_launch(void* const* d_in, const int* in_sizes, int n_in,
                              void* d_out, int out_size) {
    // Identify inputs by element count: x has NVERT*3, L has NVERT*NVERT.
    const float* x = (const float*)d_in[0];
    const float* L = (const float*)d_in[1];
    if (in_sizes[0] != NVERT * 3) {
        x = (const float*)d_in[1];
        L = (const float*)d_in[0];
    }
    float* out = (float*)d_out;

    cudaFuncSetAttribute(lap_main_kernel,
                         cudaFuncAttributeMaxDynamicSharedMemorySize,
                         (int)SMEM_BYTES);

    lap_main_kernel<<<GRID, BLOCK, SMEM_BYTES>>>(L, x, out);

    // pass2 with Programmatic Dependent Launch: its 148 blocks are prescheduled
    // during the primary's drain and start the instant the primary completes.
    cudaLaunchConfig_t cfg = {};
    cfg.gridDim  = dim3(148, 1, 1);
    cfg.blockDim = dim3(256, 1, 1);
    cfg.dynamicSmemBytes = 0;
    cfg.stream = 0;   // same (capture) stream as the primary launch
    cudaLaunchAttribute attrs[1];
    attrs[0].id = cudaLaunchAttributeProgrammaticStreamSerialization;
    attrs[0].val.programmaticStreamSerializationAllowed = 1;
    cfg.attrs = attrs;
    cfg.numAttrs = 1;
    cudaLaunchKernelEx(&cfg, pass2_kernel, out);
}